// round 17
// baseline (speedup 1.0000x reference)
#include <cuda_runtime.h>
#include <cuda_fp16.h>
#include <cstdint>

// ---------------- problem constants ----------------
#define BS     16384
#define MSEG   6
#define DM     512
#define NH     8
#define DIN    6144
#define NROWS  (BS*MSEG)            // 98304
#define QKV_ELEMS (NROWS*DM)        // 50331648
#define INV_TEMP 0.125f
#define LN_EPS 1e-6f
#define WPACK  9437184              // 512*6144*3

// ---------------- scratch ----------------
__device__ __half g_Q[QKV_ELEMS];
__device__ __half g_K[QKV_ELEMS];
__device__ __half g_V[QKV_ELEMS];
__device__ __half g_A[(size_t)BS*DIN];     // fp16 input
__device__ __half g_W[WPACK];
__device__ __half g_FW[DM*DM];
__device__ __half g_AO[QKV_ELEMS];

// per segment s
__constant__ int c_sK[6]   = {2048,1024,512,1536,768,256};
__constant__ int c_sOff[6] = {0,2048,3072,3584,5120,5888};
// weight pack offset for combo c = s*3 + w
__constant__ int c_cW[18]  = {0,1048576,2097152,3145728,3670016,4194304,
                              4718592,4980736,5242880,5505024,6291456,7077888,
                              7864320,8257536,8650752,9043968,9175040,9306112};

struct WPtrs { const float* w[18]; };
__constant__ int c_cK[18]   = {2048,2048,2048,1024,1024,1024,512,512,512,
                               1536,1536,1536,768,768,768,256,256,256};

// ---------------- helpers ----------------
__device__ __forceinline__ uint32_t smem_u32(const void* p) {
    uint32_t a;
    asm("{ .reg .u64 t; cvta.to.shared.u64 t, %1; cvt.u32.u64 %0, t; }" : "=r"(a) : "l"(p));
    return a;
}
__device__ __forceinline__ void cpa16(uint32_t s, const void* g) {
    asm volatile("cp.async.cg.shared.global [%0], [%1], 16;" :: "r"(s), "l"(g));
}
__device__ __forceinline__ void cpa_commit() { asm volatile("cp.async.commit_group;" ::: "memory"); }
__device__ __forceinline__ void cpa_wait1()  { asm volatile("cp.async.wait_group 1;" ::: "memory"); }

__device__ __forceinline__ void mma16816(float* c, const uint32_t* a, const uint32_t* b) {
    asm volatile(
        "mma.sync.aligned.m16n8k16.row.col.f32.f16.f16.f32 "
        "{%0,%1,%2,%3}, {%4,%5,%6,%7}, {%8,%9}, {%0,%1,%2,%3};"
        : "+f"(c[0]), "+f"(c[1]), "+f"(c[2]), "+f"(c[3])
        : "r"(a[0]), "r"(a[1]), "r"(a[2]), "r"(a[3]), "r"(b[0]), "r"(b[1]));
}
__device__ __forceinline__ void ldm_x4(uint32_t* r, uint32_t addr) {
    asm volatile("ldmatrix.sync.aligned.m8n8.x4.shared.b16 {%0,%1,%2,%3}, [%4];"
        : "=r"(r[0]), "=r"(r[1]), "=r"(r[2]), "=r"(r[3]) : "r"(addr));
}

// ---------------- conversion kernels ----------------
__global__ void __launch_bounds__(256) conv_input_kernel(const float* __restrict__ inp) {
    size_t i = (size_t)blockIdx.x * 256 + threadIdx.x;   // float4 index
    float4 x = ((const float4*)inp)[i];
    *(__half2*)(g_A + i*4)     = __floats2half2_rn(x.x, x.y);
    *(__half2*)(g_A + i*4 + 2) = __floats2half2_rn(x.z, x.w);
}

__global__ void __launch_bounds__(256) conv_w_kernel(WPtrs P) {
    int c = blockIdx.y;
    int n4 = (512 * c_cK[c]) >> 2;
    int i = blockIdx.x * 256 + threadIdx.x;
    if (i >= n4) return;
    float4 x = ((const float4*)P.w[c])[i];
    size_t base = (size_t)c_cW[c] + (size_t)i * 4;
    *(__half2*)(g_W + base)     = __floats2half2_rn(x.x, x.y);
    *(__half2*)(g_W + base + 2) = __floats2half2_rn(x.z, x.w);
}

__global__ void __launch_bounds__(256) conv_fcw_kernel(const float* __restrict__ fcw) {
    int i = blockIdx.x * 256 + threadIdx.x;   // 65536 float4s
    float4 x = ((const float4*)fcw)[i];
    *(__half2*)(g_FW + i*4)     = __floats2half2_rn(x.x, x.y);
    *(__half2*)(g_FW + i*4 + 2) = __floats2half2_rn(x.z, x.w);
}

// ---------------- mma.sync GEMM configuration ----------------
// CTA tile 128x128, BK=64 fp16, 1-term, 3-stage ring, one barrier/iter.
// smem buffer: 128 rows x 128B, SW128 swizzle: 16B chunk c at c ^ (r & 7).
#define BUFB   16384              // bytes per buffer (128*128)
#define STAGE_BYTES (2*BUFB)      // 32768  [A|B]
#define RING_BYTES (3*STAGE_BYTES)// 98304
#define GEMM_SMEM RING_BYTES

// FC fused: ring + 128x520-half output buffer
#define FC_OPITCH 520
#define FC_OUT_BYTES (128*FC_OPITCH*2)          // 133120
#define FC_SMEM (RING_BYTES + FC_OUT_BYTES)     // 231424

__device__ __forceinline__ void load_stage_g(
    uint32_t sbase, int tid,
    const char* A, size_t strA, const char* B, size_t strB, size_t kb)
{
#pragma unroll
    for (int j = 0; j < 4; j++) {
        int q = tid + j * 256;
        int r = q >> 3, cc = q & 7;
        uint32_t so = (uint32_t)(r * 128 + ((cc ^ (r & 7)) << 4));
        cpa16(sbase + so,        A + (size_t)r * strA + kb + cc * 16);
        cpa16(sbase + BUFB + so, B + (size_t)r * strB + kb + cc * 16);
    }
    cpa_commit();
}

struct LdmOff { uint32_t arb, akey, ach0, brb, bkey, bch0; };
__device__ __forceinline__ LdmOff ldm_offsets(int wm, int wn, int lane)
{
    LdmOff o;
    int g = lane >> 3, r8 = lane & 7;
    int arow = wm * 32 + r8 + (g & 1) * 8;
    o.arb = (uint32_t)(arow * 128); o.akey = (uint32_t)(arow & 7); o.ach0 = (uint32_t)(g >> 1);
    int brow = wn * 64 + r8 + (g >> 1) * 8;
    o.brb = (uint32_t)(brow * 128); o.bkey = (uint32_t)(brow & 7); o.bch0 = (uint32_t)(g & 1);
    return o;
}

// compute one BK=64 stage: 24 ldmatrix + 64 HMMA per warp
__device__ __forceinline__ void compute_stage(
    uint32_t sstage, const LdmOff& o, float acc[2][8][4])
{
    const uint32_t A_ = sstage, B_ = sstage + BUFB;

#pragma unroll
    for (int k16 = 0; k16 < 4; k16++) {
        uint32_t ach = ((o.ach0 + 2*k16) ^ o.akey) << 4;
        uint32_t bch = ((o.bch0 + 2*k16) ^ o.bkey) << 4;
        uint32_t ah[2][4];
#pragma unroll
        for (int mt = 0; mt < 2; mt++)
            ldm_x4(ah[mt], A_ + o.arb + ach + mt * 2048);   // 16 rows * 128B
#pragma unroll
        for (int p = 0; p < 4; p++) {
            uint32_t bb[4];
            ldm_x4(bb, B_ + o.brb + bch + p * 2048);
#pragma unroll
            for (int mt = 0; mt < 2; mt++) {
                mma16816(acc[mt][2*p],   ah[mt], bb);
                mma16816(acc[mt][2*p+1], ah[mt], bb + 2);
            }
        }
    }
}

// 3-stage ring mainloop, one barrier per iteration
__device__ __forceinline__ void gemm_mainloop(
    uint32_t sb, int tid, int nc,
    const char* A, size_t strA, const char* B, size_t strB,
    const LdmOff& o, float acc[2][8][4])
{
    load_stage_g(sb,               tid, A, strA, B, strB, 0);
    load_stage_g(sb + STAGE_BYTES, tid, A, strA, B, strB, 128);

    uint32_t stg = 0;
    for (int i = 0; i < nc; i++) {
        cpa_wait1();
        __syncthreads();
        if (i + 2 < nc) {
            uint32_t nstg = stg + 2; if (nstg >= 3) nstg -= 3;
            load_stage_g(sb + nstg * STAGE_BYTES, tid,
                         A, strA, B, strB, (size_t)(i+2) * 128);
        } else {
            cpa_commit();
        }
        compute_stage(sb + stg * STAGE_BYTES, o, acc);
        if (++stg == 3) stg = 0;
    }
    __syncthreads();
}

// write acc tile to smem as fp16, generic pitch/col offset (conflict-free:
// pitch%64 halves == 8 -> bank = l4*4+lm, all distinct)
#define TPITCH 136

__device__ __forceinline__ void acc_to_smem_h(
    __half* tb, int pitch, int c0, int wm, int wn, int lane, float acc[2][8][4])
{
    const int l4 = lane >> 2, lm = lane & 3;
#pragma unroll
    for (int mt = 0; mt < 2; mt++)
#pragma unroll
        for (int nt = 0; nt < 8; nt++) {
            int R = wm*32 + mt*16 + l4;
            int C = c0 + wn*64 + nt*8 + lm*2;
            *(__half2*)(tb + R*pitch + C)     = __floats2half2_rn(acc[mt][nt][0], acc[mt][nt][1]);
            *(__half2*)(tb + (R+8)*pitch + C) = __floats2half2_rn(acc[mt][nt][2], acc[mt][nt][3]);
        }
}

// ---------------- QKV GEMM ----------------
// grid (12 ntiles = q|k|v x 4, 128 mtiles, 6 segments), 256 threads. Output fp16.
__global__ void __launch_bounds__(256, 2)
qkv_mma_kernel()
{
    extern __shared__ char smem[];
    const uint32_t sb = smem_u32(smem);
    const int tid = threadIdx.x, wid = tid >> 5, lane = tid & 31;
    const int wm = wid & 3, wn = wid >> 2;
    const int nG = blockIdx.x * 128;        // 0..1535
    const int m0 = blockIdx.y * 128;
    const int s  = blockIdx.z;
    const int w  = nG >> 9;                 // 0=q 1=k 2=v
    const int n0 = nG & 511;
    const int Kdim = c_sK[s];
    const int seg  = c_sOff[s];
    const int nc = Kdim >> 6;

    const char* A = (const char*)(g_A + (size_t)m0 * DIN + seg);
    const char* B = (const char*)(g_W + (size_t)c_cW[s*3 + w] + (size_t)n0 * Kdim);
    const size_t strA = (size_t)DIN * 2, strB = (size_t)Kdim * 2;

    LdmOff o = ldm_offsets(wm, wn, lane);

    float acc[2][8][4];
#pragma unroll
    for (int i = 0; i < 2; i++)
#pragma unroll
        for (int j = 0; j < 8; j++)
#pragma unroll
            for (int k = 0; k < 4; k++) acc[i][j][k] = 0.0f;

    gemm_mainloop(sb, tid, nc, A, strA, B, strB, o, acc);

    // epilogue: acc -> fp16 smem -> coalesced fp16 global
    __half* tb = (__half*)smem;
    acc_to_smem_h(tb, TPITCH, 0, wm, wn, lane, acc);
    __syncthreads();
    __half* Cb = (w == 0) ? g_Q : (w == 1) ? g_K : g_V;
#pragma unroll
    for (int it = 0; it < 8; it++) {
        int v = tid + it * 256;                // 2048 chunks of 8 halves
        int rr = v >> 4, c8 = (v & 15) * 8;
        uint4 d = *(const uint4*)(tb + rr*TPITCH + c8);
        *(uint4*)(Cb + ((size_t)(m0 + rr) * MSEG + s) * DM + n0 + c8) = d;
    }
}

// ---------------- FC GEMM + bias + residual + LayerNorm (fused) ----------------
// grid (768 mtiles), 256 threads, 1 CTA/SM. Each CTA owns 128 complete rows:
// loops 4 n-tiles through the ring, collects fp16 results in a 128x520 smem
// buffer, then LayerNorms in-CTA and writes fp32 directly to d_out.
__global__ void __launch_bounds__(256, 1)
fc_ln_kernel(const float* __restrict__ fcb, float* __restrict__ outp,
             const float* __restrict__ lng, const float* __restrict__ lnb)
{
    extern __shared__ char smem[];
    const uint32_t sb = smem_u32(smem);
    const int tid = threadIdx.x, wid = tid >> 5, lane = tid & 31;
    const int wm = wid & 3, wn = wid >> 2;
    const int m0 = blockIdx.x * 128;

    const char* A = (const char*)(g_AO + (size_t)m0 * DM);
    const size_t strA = (size_t)DM * 2, strB = (size_t)DM * 2;

    LdmOff o = ldm_offsets(wm, wn, lane);
    __half* ob = (__half*)(smem + RING_BYTES);

#pragma unroll 1
    for (int t = 0; t < 4; t++) {
        const char* B = (const char*)(g_FW + (size_t)(t * 128) * DM);
        float acc[2][8][4];
#pragma unroll
        for (int i = 0; i < 2; i++)
#pragma unroll
            for (int j = 0; j < 8; j++)
#pragma unroll
                for (int k = 0; k < 4; k++) acc[i][j][k] = 0.0f;

        gemm_mainloop(sb, tid, 8, A, strA, B, strB, o, acc);
        acc_to_smem_h(ob, FC_OPITCH, t * 128, wm, wn, lane, acc);
    }
    __syncthreads();

    // LayerNorm: warp w handles rows w*16 .. w*16+15
    for (int r16 = 0; r16 < 16; r16++) {
        int row = wid * 16 + r16;
        int m = m0 + row;
        const __half2* rp = (const __half2*)(ob + row * FC_OPITCH);
        const __half2* vp = (const __half2*)(g_V + (size_t)m * DM);

        float2 x[8];
        float s = 0.0f, sq = 0.0f;
#pragma unroll
        for (int j = 0; j < 8; j++) {
            int c2 = lane + 32 * j;
            float2 xv = __half22float2(rp[c2]);
            float2 vv = __half22float2(vp[c2]);
            float2 bv = ((const float2*)fcb)[c2];
            xv.x += vv.x + bv.x;
            xv.y += vv.y + bv.y;
            x[j] = xv;
            s  += xv.x + xv.y;
            sq += xv.x*xv.x + xv.y*xv.y;
        }
#pragma unroll
        for (int off = 16; off > 0; off >>= 1) {
            s  += __shfl_xor_sync(0xffffffffu, s,  off);
            sq += __shfl_xor_sync(0xffffffffu, sq, off);
        }
        float mu  = s * (1.0f / DM);
        float var = sq * (1.0f / DM) - mu * mu;
        float rstd = rsqrtf(var + LN_EPS);

        float2* op = (float2*)(outp + (size_t)m * DM);
#pragma unroll
        for (int j = 0; j < 8; j++) {
            int c2 = lane + 32 * j;
            float2 gg = ((const float2*)lng)[c2];
            float2 bb = ((const float2*)lnb)[c2];
            float2 ov;
            ov.x = (x[j].x - mu) * rstd * gg.x + bb.x;
            ov.y = (x[j].y - mu) * rstd * gg.y + bb.y;
            op[c2] = ov;
        }
    }
}

// ---------------- fused attention (half2 vectorized) ----------------
// attn/|global min| then row-L2-normalize: the scale cancels (v*s/||v*s|| = v/||v||,
// s>0), so no cross-batch pass is needed. Q/K/V fp16 in, AO fp16 out.
__global__ void __launch_bounds__(256)
attn_kernel(float* __restrict__ attn_out)
{
    const int b    = blockIdx.x;
    const int tid  = threadIdx.x;
    const int h    = tid >> 5;
    const int lane = tid & 31;

    __shared__ float at[NH*36];

    const __half2* Qb = (const __half2*)(g_Q + (size_t)b * (MSEG*DM) + h * 64) + lane;
    const __half2* Kb = (const __half2*)(g_K + (size_t)b * (MSEG*DM) + h * 64) + lane;

    float2 q[6], k[6];
#pragma unroll
    for (int t = 0; t < 6; t++) {
        q[t] = __half22float2(Qb[t*(DM/2)]);
        k[t] = __half22float2(Kb[t*(DM/2)]);
    }

#pragma unroll
    for (int tq = 0; tq < 6; tq++) {
#pragma unroll
        for (int tk = 0; tk < 6; tk++) {
            float p = q[tq].x*k[tk].x + q[tq].y*k[tk].y;
#pragma unroll
            for (int o = 16; o > 0; o >>= 1)
                p += __shfl_xor_sync(0xffffffffu, p, o);
            if (lane == 0) at[h*36 + tq*6 + tk] = p * INV_TEMP;
        }
    }
    __syncthreads();

    if (tid < 48) {
        int hh = tid / 6, tq = tid % 6;
        float* lp = &at[hh*36 + tq*6];
        float v[6]; float ss = 0.0f;
#pragma unroll
        for (int kk = 0; kk < 6; kk++) { v[kk] = lp[kk]; ss += v[kk]*v[kk]; }
        float inorm = 1.0f / fmaxf(sqrtf(ss), 1e-30f);
        float mx = -3.4e38f;
#pragma unroll
        for (int kk = 0; kk < 6; kk++) { v[kk] *= inorm; mx = fmaxf(mx, v[kk]); }
        float es = 0.0f; float e[6];
#pragma unroll
        for (int kk = 0; kk < 6; kk++) { e[kk] = expf(v[kk] - mx); es += e[kk]; }
        float r = 1.0f / es;
        float* ao = attn_out + ((size_t)b * NH + hh) * 36 + tq * 6;
#pragma unroll
        for (int kk = 0; kk < 6; kk++) {
            float a = e[kk] * r;
            lp[kk] = a;
            ao[kk] = a;
        }
    }
    __syncthreads();

    // AO[b,t,f] = sum_k attn[h,t,k] * V[b,k,f] ; half2 over f
    const __half2* Vb = (const __half2*)(g_V + (size_t)b * (MSEG*DM));
    __half2* AOb = (__half2*)(g_AO + (size_t)b * (MSEG*DM));
    for (int idx = tid; idx < MSEG*(DM/2); idx += 256) {
        int t  = idx >> 8;            // / 256
        int f2 = idx & 255;
        int hh = f2 >> 5;             // (2*f2) >> 6
        const float* ar = &at[hh*36 + t*6];
        float sx = 0.0f, sy = 0.0f;
#pragma unroll
        for (int kk = 0; kk < 6; kk++) {
            float2 vv = __half22float2(Vb[kk*(DM/2) + f2]);
            sx += ar[kk] * vv.x;
            sy += ar[kk] * vv.y;
        }
        AOb[idx] = __floats2half2_rn(sx, sy);
    }
}

// ---------------- launch ----------------
extern "C" void kernel_launch(void* const* d_in, const int* in_sizes, int n_in,
                              void* d_out, int out_size)
{
    const float* inp = (const float*)d_in[0];
    WPtrs P;
    for (int i = 0; i < 18; i++) P.w[i] = (const float*)d_in[1 + i];
    const float* fc_w = (const float*)d_in[19];
    const float* fc_b = (const float*)d_in[20];
    const float* ln_g = (const float*)d_in[21];
    const float* ln_b = (const float*)d_in[22];

    float* outp     = (float*)d_out;
    float* attn_out = outp + (size_t)NROWS * DM;

    cudaFuncSetAttribute(qkv_mma_kernel, cudaFuncAttributeMaxDynamicSharedMemorySize, GEMM_SMEM);
    cudaFuncSetAttribute(fc_ln_kernel,   cudaFuncAttributeMaxDynamicSharedMemorySize, FC_SMEM);

    conv_input_kernel<<<(BS*(size_t)DIN/4 + 255)/256, 256>>>(inp);
    conv_w_kernel<<<dim3(1024, 18), 256>>>(P);
    conv_fcw_kernel<<<256, 256>>>(fc_w);
    qkv_mma_kernel<<<dim3(12, 128, 6), 256, GEMM_SMEM>>>();
    attn_kernel<<<BS, 256>>>(attn_out);
    fc_ln_kernel<<<768, 256, FC_SMEM>>>(fc_b, outp, ln_g, ln_b);
}